// round 1
// baseline (speedup 1.0000x reference)
#include <cuda_runtime.h>
#include <cuda_bf16.h>

// ModuleSoftsplat: forward (summation) splatting.
// image [B=4, C=64, H=512, W=512] f32, flow [B, 2, H, W] f32 -> out [B, C, H, W] f32
// out[b,c,y1,x1] += image[b,c,y,x] * w_bilinear, scattered at (x + flow_x, y + flow_y).

#define SS_B 4
#define SS_C 64
#define SS_H 512
#define SS_W 512
#define SS_HW (SS_H * SS_W)          // 262144
#define SS_CHW (SS_C * SS_HW)        // 16777216

// ---------------------------------------------------------------------------
// Zero-fill output (float4 stores, grid-stride)
// ---------------------------------------------------------------------------
__global__ __launch_bounds__(256) void ss_zero_kernel(float4* __restrict__ out, int n4) {
    int i = blockIdx.x * blockDim.x + threadIdx.x;
    int stride = gridDim.x * blockDim.x;
    float4 z = make_float4(0.f, 0.f, 0.f, 0.f);
    for (; i < n4; i += stride) out[i] = z;
}

// ---------------------------------------------------------------------------
// Scatter splat. One thread per (b, y, x); inner loop over C channels.
// Grid: B*H*(W/256) blocks of 256 threads.
// ---------------------------------------------------------------------------
__global__ __launch_bounds__(256) void ss_splat_kernel(
    const float* __restrict__ img,
    const float* __restrict__ flow,
    float* __restrict__ out)
{
    // Decompose block id: [b][y][xblk], xblk in {0,1}
    int gid  = blockIdx.x;
    int xblk = gid & 1;
    int y    = (gid >> 1) & (SS_H - 1);
    int b    = gid >> 10;                  // gid / (2*512)
    int x    = xblk * 256 + threadIdx.x;

    // Load flow once per pixel (shared across all 64 channels)
    int fbase = (b * 2) * SS_HW + y * SS_W + x;
    float fx = flow[fbase] + (float)x;
    float fy = flow[fbase + SS_HW] + (float)y;

    float x0f = floorf(fx);
    float y0f = floorf(fy);
    int x0 = (int)x0f;
    int y0 = (int)y0f;
    float wx1 = fx - x0f;
    float wx0 = 1.0f - wx1;
    float wy1 = fy - y0f;
    float wy0 = 1.0f - wy1;

    int x1 = x0 + 1;
    int y1 = y0 + 1;

    bool vx0 = (x0 >= 0) & (x0 < SS_W);
    bool vx1 = (x1 >= 0) & (x1 < SS_W);
    bool vy0 = (y0 >= 0) & (y0 < SS_H);
    bool vy1 = (y1 >= 0) & (y1 < SS_H);

    // 4 neighbors: weight and spatial index (only used when valid)
    float w00 = wx0 * wy0;   // (x0, y0)
    float w10 = wx1 * wy0;   // (x1, y0)
    float w01 = wx0 * wy1;   // (x0, y1)
    float w11 = wx1 * wy1;   // (x1, y1)

    bool v00 = vx0 & vy0;
    bool v10 = vx1 & vy0;
    bool v01 = vx0 & vy1;
    bool v11 = vx1 & vy1;

    // Clamp for safe address formation (matches reference's clip; weight gates contribution,
    // but we skip the atomic entirely when invalid).
    int cx0 = min(max(x0, 0), SS_W - 1);
    int cx1 = min(max(x1, 0), SS_W - 1);
    int cy0 = min(max(y0, 0), SS_H - 1);
    int cy1 = min(max(y1, 0), SS_H - 1);

    int i00 = cy0 * SS_W + cx0;
    int i10 = cy0 * SS_W + cx1;
    int i01 = cy1 * SS_W + cx0;
    int i11 = cy1 * SS_W + cx1;

    const float* ip = img + (long long)b * SS_CHW + y * SS_W + x;
    float* op = out + (long long)b * SS_CHW;

    #pragma unroll 4
    for (int c = 0; c < SS_C; c++) {
        float v = ip[c * SS_HW];
        float* oc = op + c * SS_HW;
        if (v00) atomicAdd(oc + i00, v * w00);
        if (v10) atomicAdd(oc + i10, v * w10);
        if (v01) atomicAdd(oc + i01, v * w01);
        if (v11) atomicAdd(oc + i11, v * w11);
    }
}

// ---------------------------------------------------------------------------
// Launch
// ---------------------------------------------------------------------------
extern "C" void kernel_launch(void* const* d_in, const int* in_sizes, int n_in,
                              void* d_out, int out_size) {
    const float* img  = (const float*)d_in[0];   // [4,64,512,512]
    const float* flow = (const float*)d_in[1];   // [4,2,512,512]
    float* out = (float*)d_out;                  // [4,64,512,512]

    int n4 = out_size / 4;                       // 16,777,216 float4s
    ss_zero_kernel<<<8192, 256>>>((float4*)out, n4);

    int nblk = SS_B * SS_H * (SS_W / 256);       // 4096
    ss_splat_kernel<<<nblk, 256>>>(img, flow, out);
}

// round 2
// speedup vs baseline: 1.5698x; 1.5698x over previous
#include <cuda_runtime.h>

// ModuleSoftsplat forward summation splatting, gather formulation.
// image [4,64,512,512] f32, flow [4,2,512,512] f32 -> out [4,64,512,512] f32.
//
// Instead of 268M global atomics (L2 atomic-ALU bound), each CTA owns a 32x32
// dest tile: it bins contributors from the 48x48 source halo into per-cell
// smem lists ONCE (shared across channels), then for each channel stages the
// image halo into smem and computes every dest cell with a plain store.
// Contributions that can't be captured by the halo/bin capacity go to a
// global overflow list (worst-case-sized, so nothing is ever dropped) and are
// splatted by a small atomic kernel afterward.

#define SS_B   4
#define SS_C   64
#define SS_H   512
#define SS_W   512
#define SS_HW  (SS_H * SS_W)          // 262144 = 2^18
#define SS_CHW (SS_C * SS_HW)

#define TS     32                     // dest tile side
#define HALO   8                      // capture radius for sources
#define RW     (TS + 2 * HALO)        // 48: source region side
#define RN     (RW * RW)              // 2304
#define RPITCH 49                     // padded smem row pitch
#define KCAP   9                      // bin slots per dest cell
#define NCELLS (TS * TS)              // 1024
#define NGRP   2                      // channel groups (32 ch each)
#define CHG    (SS_C / NGRP)          // 32

// Worst case: every (source, neighbor) attempt overflows, per group.
#define OVF_CAP (NGRP * 4 * SS_B * SS_HW)   // 8,388,608

#define SMEM_BYTES (NCELLS * 4 + NCELLS * KCAP * 8 + RW * RPITCH * 8)  // 96,640

__device__ int   g_ovf_n;
__device__ int   g_ovf_cell[OVF_CAP];   // (grp<<20) | (b<<18) | (y<<9) | x
__device__ int   g_ovf_src [OVF_CAP];   // (b<<18) | spatial
__device__ float g_ovf_w   [OVF_CAP];

__device__ __forceinline__ void ovf_append(int cellp, int src, float w) {
    int slot = atomicAdd(&g_ovf_n, 1);
    if (slot < OVF_CAP) {
        g_ovf_cell[slot] = cellp;
        g_ovf_src [slot] = src;
        g_ovf_w   [slot] = w;
    }
}

__global__ void ss_reset_kernel() { g_ovf_n = 0; }

// ---------------------------------------------------------------------------
// Main tiled gather kernel. Grid: 2048 = b(2) | grp(1) | ty(4) | tx(4).
// ---------------------------------------------------------------------------
__global__ __launch_bounds__(256, 2) void ss_gather_kernel(
    const float* __restrict__ img,
    const float* __restrict__ flow,
    float* __restrict__ out)
{
    extern __shared__ unsigned char sraw[];
    int*    s_cnt = (int*)sraw;                                   // 1024 ints
    uint2*  s_bin = (uint2*)(sraw + NCELLS * 4);                  // 1024*9 entries
    float2* s_img = (float2*)(sraw + NCELLS * 4 + NCELLS * KCAP * 8); // 48*49

    const int tid = threadIdx.x;
    const int bi  = blockIdx.x;
    const int tx0 = (bi & 15) * TS;
    const int ty0 = ((bi >> 4) & 15) * TS;
    const int grp = (bi >> 8) & 1;
    const int b   = bi >> 9;

    for (int i = tid; i < NCELLS; i += 256) s_cnt[i] = 0;
    __syncthreads();

    // -------- Phase A: bin contributors (channel-independent) --------
    const float* flowb = flow + (size_t)b * 2 * SS_HW;
    for (int i = tid; i < RN; i += 256) {
        int ly = i / RW, lx = i - ly * RW;
        int gy = ty0 - HALO + ly, gx = tx0 - HALO + lx;
        if ((unsigned)gx >= SS_W || (unsigned)gy >= SS_H) continue;
        int sp = gy * SS_W + gx;
        float fx = flowb[sp]         + (float)gx;
        float fy = flowb[sp + SS_HW] + (float)gy;
        float x0f = floorf(fx), y0f = floorf(fy);
        int x0 = (int)x0f, y0 = (int)y0f;
        float wx1 = fx - x0f, wx0 = 1.0f - wx1;
        float wy1 = fy - y0f, wy0 = 1.0f - wy1;
        int sidx = ly * RPITCH + lx;
        bool own = (gx >= tx0) && (gx < tx0 + TS) && (gy >= ty0) && (gy < ty0 + TS);
        #pragma unroll
        for (int k = 0; k < 4; k++) {
            int dx = k & 1, dy = k >> 1;
            int cx = x0 + dx, cy = y0 + dy;
            if ((unsigned)cx >= SS_W || (unsigned)cy >= SS_H) continue;
            float w = (dx ? wx1 : wx0) * (dy ? wy1 : wy0);
            int lcx = cx - tx0, lcy = cy - ty0;
            if ((unsigned)lcx < TS && (unsigned)lcy < TS) {
                int cid  = lcy * TS + lcx;
                int slot = atomicAdd(&s_cnt[cid], 1);
                if (slot < KCAP)
                    s_bin[cid * KCAP + slot] =
                        make_uint2(__float_as_uint(w), (unsigned)sidx);
                else
                    ovf_append((grp << 20) | (b << 18) | (cy << 9) | cx,
                               (b << 18) | sp, w);
            } else if (own) {
                // Will the tile owning (cx,cy) capture this source in its halo?
                int tcx = cx & ~(TS - 1), tcy = cy & ~(TS - 1);
                bool cap = (gx >= tcx - HALO) && (gx < tcx + TS + HALO) &&
                           (gy >= tcy - HALO) && (gy < tcy + TS + HALO);
                if (!cap)
                    ovf_append((grp << 20) | (b << 18) | (cy << 9) | cx,
                               (b << 18) | sp, w);
            }
        }
    }
    __syncthreads();

    int n0 = min(s_cnt[tid      ], KCAP);
    int n1 = min(s_cnt[tid + 256], KCAP);
    int n2 = min(s_cnt[tid + 512], KCAP);
    int n3 = min(s_cnt[tid + 768], KCAP);

    // -------- Phase B: per-channel-pair stage + gather --------
    const float* imgb = img + (size_t)b * SS_CHW;
    float*       outb = out + (size_t)b * SS_CHW;
    const int cbase = grp * CHG;

    for (int cp = 0; cp < CHG; cp += 2) {
        const float* ic0 = imgb + (size_t)(cbase + cp) * SS_HW;
        const float* ic1 = ic0 + SS_HW;
        for (int i = tid; i < RN; i += 256) {
            int ly = i / RW, lx = i - ly * RW;
            int gy = ty0 - HALO + ly, gx = tx0 - HALO + lx;
            float v0 = 0.f, v1 = 0.f;
            if ((unsigned)gx < SS_W && (unsigned)gy < SS_H) {
                int g = gy * SS_W + gx;
                v0 = ic0[g];
                v1 = ic1[g];
            }
            s_img[ly * RPITCH + lx] = make_float2(v0, v1);
        }
        __syncthreads();

        float* o0 = outb + (size_t)(cbase + cp) * SS_HW;
        float* o1 = o0 + SS_HW;
        #pragma unroll
        for (int k = 0; k < 4; k++) {
            int cid = tid + k * 256;
            int n   = (k == 0) ? n0 : (k == 1) ? n1 : (k == 2) ? n2 : n3;
            float a0 = 0.f, a1 = 0.f;
            for (int i = 0; i < n; i++) {
                uint2  e = s_bin[cid * KCAP + i];
                float  w = __uint_as_float(e.x);
                float2 v = s_img[e.y];
                a0 += w * v.x;
                a1 += w * v.y;
            }
            int g = (ty0 + (cid >> 5)) * SS_W + tx0 + (cid & 31);
            o0[g] = a0;
            o1[g] = a1;
        }
        __syncthreads();
    }
}

// ---------------------------------------------------------------------------
// Overflow splat: rare contributions, global atomics. Group-tagged so each
// entry applies only to its group's 32 channels (bins are per-group).
// ---------------------------------------------------------------------------
__global__ __launch_bounds__(256) void ss_ovf_kernel(
    const float* __restrict__ img, float* __restrict__ out)
{
    int n = g_ovf_n;
    if (n > OVF_CAP) n = OVF_CAP;
    long long total = (long long)n * CHG;
    long long stride = (long long)gridDim.x * blockDim.x;
    for (long long i = blockIdx.x * (long long)blockDim.x + threadIdx.x;
         i < total; i += stride) {
        int e  = (int)(i >> 5);        // /32
        int c  = (int)(i & 31);
        int cellp = g_ovf_cell[e];
        int grp   = (cellp >> 20) & 1;
        int bb    = (cellp >> 18) & 3;
        int sp    = cellp & (SS_HW - 1);
        int src   = g_ovf_src[e];
        int ssp   = src & (SS_HW - 1);
        int ch    = grp * CHG + c;
        size_t plane = (size_t)bb * SS_CHW + (size_t)ch * SS_HW;
        atomicAdd(out + plane + sp, img[plane + ssp] * g_ovf_w[e]);
    }
}

// ---------------------------------------------------------------------------
extern "C" void kernel_launch(void* const* d_in, const int* in_sizes, int n_in,
                              void* d_out, int out_size) {
    const float* img  = (const float*)d_in[0];
    const float* flow = (const float*)d_in[1];
    float* out = (float*)d_out;

    cudaFuncSetAttribute(ss_gather_kernel,
                         cudaFuncAttributeMaxDynamicSharedMemorySize, SMEM_BYTES);

    ss_reset_kernel<<<1, 1>>>();
    ss_gather_kernel<<<SS_B * NGRP * 16 * 16, 256, SMEM_BYTES>>>(img, flow, out);
    ss_ovf_kernel<<<512, 256>>>(img, out);
}

// round 6
// speedup vs baseline: 2.2983x; 1.4640x over previous
#include <cuda_runtime.h>

// ModuleSoftsplat forward summation splatting, tiled-gather formulation v3.
// image [4,64,512,512] f32, flow [4,2,512,512] f32 -> out [4,64,512,512] f32.
//
// Each CTA owns a 32x32 dest tile and ALL 64 channels:
//   Phase A (once per tile): bin contributors from the 48x48 source halo into
//     per-cell smem lists (smem atomics only for slot assignment).
//   Phase B (16 passes of 4 channels): stage the 48x48 image halo as float4
//     (4 channels interleaved), then each dest cell accumulates its <=9
//     contributors via LDS and writes with plain coalesced stores.
// Contributions not capturable (halo miss or bin overflow) go to a
// worst-case-sized global list, splatted by a small atomic kernel.

#define SS_B   4
#define SS_C   64
#define SS_H   512
#define SS_W   512
#define SS_HW  (SS_H * SS_W)
#define SS_CHW (SS_C * SS_HW)

#define TS     32
#define HALO   8
#define RW     (TS + 2 * HALO)        // 48
#define RN     (RW * RW)              // 2304
#define KCAP   9
#define NCELLS (TS * TS)              // 1024

#define OVF_CAP (4 * SS_B * SS_HW)    // 4,194,304 (worst case, nothing dropped)

// smem: cnt 4096 + bin 73728 + img 48*48*16 = 114688 bytes
#define SM_BIN_OFF  (NCELLS * 4)
#define SM_IMG_OFF  (SM_BIN_OFF + NCELLS * KCAP * 8)
#define SMEM_BYTES  (SM_IMG_OFF + RN * 16)

__device__ int   g_ovf_n;
__device__ int   g_ovf_cell[OVF_CAP];   // (b<<18) | (y<<9) | x
__device__ int   g_ovf_src [OVF_CAP];   // (b<<18) | spatial
__device__ float g_ovf_w   [OVF_CAP];

__device__ __forceinline__ void ovf_append(int cellp, int src, float w) {
    int slot = atomicAdd(&g_ovf_n, 1);
    if (slot < OVF_CAP) {
        g_ovf_cell[slot] = cellp;
        g_ovf_src [slot] = src;
        g_ovf_w   [slot] = w;
    }
}

__global__ void ss_reset_kernel() { g_ovf_n = 0; }

// ---------------------------------------------------------------------------
// Main tiled gather kernel. Grid: 1024 = b(2) | ty(4) | tx(4).
// ---------------------------------------------------------------------------
__global__ __launch_bounds__(256, 2) void ss_gather_kernel(
    const float* __restrict__ img,
    const float* __restrict__ flow,
    float* __restrict__ out)
{
    extern __shared__ unsigned char sraw[];
    int*    s_cnt = (int*)sraw;
    uint2*  s_bin = (uint2*)(sraw + SM_BIN_OFF);
    float4* s_img = (float4*)(sraw + SM_IMG_OFF);

    const int tid = threadIdx.x;
    const int bi  = blockIdx.x;
    const int tx0 = (bi & 15) * TS;
    const int ty0 = ((bi >> 4) & 15) * TS;
    const int b   = bi >> 8;

    for (int i = tid; i < NCELLS; i += 256) s_cnt[i] = 0;
    __syncthreads();

    // -------- Phase A: bin contributors (channel-independent, once) --------
    const float* flowb = flow + (size_t)b * 2 * SS_HW;
    #pragma unroll
    for (int it = 0; it < RN / 256; it++) {
        int i  = tid + it * 256;
        int ly = i / RW, lx = i - ly * RW;
        int gy = ty0 - HALO + ly, gx = tx0 - HALO + lx;
        if ((unsigned)gx >= SS_W || (unsigned)gy >= SS_H) continue;
        int sp = (gy << 9) + gx;
        float fx = flowb[sp]         + (float)gx;
        float fy = flowb[sp + SS_HW] + (float)gy;
        float x0f = floorf(fx), y0f = floorf(fy);
        int x0 = (int)x0f, y0 = (int)y0f;
        float wx1 = fx - x0f, wx0 = 1.0f - wx1;
        float wy1 = fy - y0f, wy0 = 1.0f - wy1;
        int sidx = ly * RW + lx;
        bool own = (gx >= tx0) && (gx < tx0 + TS) && (gy >= ty0) && (gy < ty0 + TS);
        #pragma unroll
        for (int k = 0; k < 4; k++) {
            int dx = k & 1, dy = k >> 1;
            int cx = x0 + dx, cy = y0 + dy;
            if ((unsigned)cx >= SS_W || (unsigned)cy >= SS_H) continue;
            float w = (dx ? wx1 : wx0) * (dy ? wy1 : wy0);
            int lcx = cx - tx0, lcy = cy - ty0;
            if ((unsigned)lcx < TS && (unsigned)lcy < TS) {
                int cid  = (lcy << 5) + lcx;
                int slot = atomicAdd(&s_cnt[cid], 1);
                if (slot < KCAP)
                    s_bin[cid * KCAP + slot] =
                        make_uint2(__float_as_uint(w), (unsigned)sidx);
                else
                    ovf_append((b << 18) | (cy << 9) | cx, (b << 18) | sp, w);
            } else if (own) {
                int tcx = cx & ~(TS - 1), tcy = cy & ~(TS - 1);
                bool cap = (gx >= tcx - HALO) && (gx < tcx + TS + HALO) &&
                           (gy >= tcy - HALO) && (gy < tcy + TS + HALO);
                if (!cap)
                    ovf_append((b << 18) | (cy << 9) | cx, (b << 18) | sp, w);
            }
        }
    }
    __syncthreads();

    const int n0 = min(s_cnt[tid      ], KCAP);
    const int n1 = min(s_cnt[tid + 256], KCAP);
    const int n2 = min(s_cnt[tid + 512], KCAP);
    const int n3 = min(s_cnt[tid + 768], KCAP);
    const int nmax = max(max(n0, n1), max(n2, n3));

    const uint2* bp0 = s_bin + (size_t)(tid      ) * KCAP;
    const uint2* bp1 = s_bin + (size_t)(tid + 256) * KCAP;
    const uint2* bp2 = s_bin + (size_t)(tid + 512) * KCAP;
    const uint2* bp3 = s_bin + (size_t)(tid + 768) * KCAP;

    // Output spatial offsets for this thread's 4 cells (coalesced per warp)
    const int g0 = ((ty0 + ((tid      ) >> 5)) << 9) + tx0 + (tid & 31);
    const int g1 = g0 + (256 >> 5) * SS_W;   // +8 rows
    const int g2 = g1 + (256 >> 5) * SS_W;
    const int g3 = g2 + (256 >> 5) * SS_W;

    const bool interior = (tx0 >= HALO) && (tx0 + TS + HALO <= SS_W) &&
                          (ty0 >= HALO) && (ty0 + TS + HALO <= SS_H);
    const int rbase = ((ty0 - HALO) << 9) + (tx0 - HALO);

    const float* imgb = img + (size_t)b * SS_CHW;
    float*       outb = out + (size_t)b * SS_CHW;

    // -------- Phase B: 16 passes of 4 channels --------
    for (int c4 = 0; c4 < SS_C; c4 += 4) {
        const float* ic0 = imgb + (size_t)c4 * SS_HW;
        const float* ic1 = ic0 + SS_HW;
        const float* ic2 = ic1 + SS_HW;
        const float* ic3 = ic2 + SS_HW;

        if (interior) {
            #pragma unroll
            for (int it = 0; it < RN / 256; it++) {
                int i  = tid + it * 256;
                int ly = i / RW, lx = i - ly * RW;
                int g  = rbase + (ly << 9) + lx;
                s_img[i] = make_float4(ic0[g], ic1[g], ic2[g], ic3[g]);
            }
        } else {
            #pragma unroll
            for (int it = 0; it < RN / 256; it++) {
                int i  = tid + it * 256;
                int ly = i / RW, lx = i - ly * RW;
                int gy = ty0 - HALO + ly, gx = tx0 - HALO + lx;
                float4 v = make_float4(0.f, 0.f, 0.f, 0.f);
                if ((unsigned)gx < SS_W && (unsigned)gy < SS_H) {
                    int g = (gy << 9) + gx;
                    v = make_float4(ic0[g], ic1[g], ic2[g], ic3[g]);
                }
                s_img[i] = v;
            }
        }
        __syncthreads();

        float4 A0 = make_float4(0.f, 0.f, 0.f, 0.f);
        float4 A1 = A0, A2 = A0, A3 = A0;

        // Interleaved over the 4 owned cells: up to 8 LDS in flight/iteration
        for (int i = 0; i < nmax; i++) {
            if (i < n0) {
                uint2 e = bp0[i]; float w = __uint_as_float(e.x);
                float4 v = s_img[e.y];
                A0.x += w * v.x; A0.y += w * v.y; A0.z += w * v.z; A0.w += w * v.w;
            }
            if (i < n1) {
                uint2 e = bp1[i]; float w = __uint_as_float(e.x);
                float4 v = s_img[e.y];
                A1.x += w * v.x; A1.y += w * v.y; A1.z += w * v.z; A1.w += w * v.w;
            }
            if (i < n2) {
                uint2 e = bp2[i]; float w = __uint_as_float(e.x);
                float4 v = s_img[e.y];
                A2.x += w * v.x; A2.y += w * v.y; A2.z += w * v.z; A2.w += w * v.w;
            }
            if (i < n3) {
                uint2 e = bp3[i]; float w = __uint_as_float(e.x);
                float4 v = s_img[e.y];
                A3.x += w * v.x; A3.y += w * v.y; A3.z += w * v.z; A3.w += w * v.w;
            }
        }

        float* o0 = outb + (size_t)c4 * SS_HW;
        float* o1 = o0 + SS_HW;
        float* o2 = o1 + SS_HW;
        float* o3 = o2 + SS_HW;
        __stcs(o0 + g0, A0.x); __stcs(o1 + g0, A0.y); __stcs(o2 + g0, A0.z); __stcs(o3 + g0, A0.w);
        __stcs(o0 + g1, A1.x); __stcs(o1 + g1, A1.y); __stcs(o2 + g1, A1.z); __stcs(o3 + g1, A1.w);
        __stcs(o0 + g2, A2.x); __stcs(o1 + g2, A2.y); __stcs(o2 + g2, A2.z); __stcs(o3 + g2, A2.w);
        __stcs(o0 + g3, A3.x); __stcs(o1 + g3, A3.y); __stcs(o2 + g3, A3.z); __stcs(o3 + g3, A3.w);
        __syncthreads();
    }
}

// ---------------------------------------------------------------------------
// Overflow splat: rare contributions, global atomics, all 64 channels.
// ---------------------------------------------------------------------------
__global__ __launch_bounds__(256) void ss_ovf_kernel(
    const float* __restrict__ img, float* __restrict__ out)
{
    int n = g_ovf_n;
    if (n > OVF_CAP) n = OVF_CAP;
    long long total = (long long)n * SS_C;
    long long stride = (long long)gridDim.x * blockDim.x;
    for (long long i = blockIdx.x * (long long)blockDim.x + threadIdx.x;
         i < total; i += stride) {
        int e  = (int)(i >> 6);        // / 64
        int c  = (int)(i & 63);
        int cellp = g_ovf_cell[e];
        int bb    = (cellp >> 18) & 3;
        int sp    = cellp & (SS_HW - 1);
        int ssp   = g_ovf_src[e] & (SS_HW - 1);
        size_t plane = (size_t)bb * SS_CHW + (size_t)c * SS_HW;
        atomicAdd(out + plane + sp, img[plane + ssp] * g_ovf_w[e]);
    }
}

// ---------------------------------------------------------------------------
extern "C" void kernel_launch(void* const* d_in, const int* in_sizes, int n_in,
                              void* d_out, int out_size) {
    const float* img  = (const float*)d_in[0];
    const float* flow = (const float*)d_in[1];
    float* out = (float*)d_out;

    cudaFuncSetAttribute(ss_gather_kernel,
                         cudaFuncAttributeMaxDynamicSharedMemorySize, SMEM_BYTES);

    // Order: gather, ovf, then reset for the NEXT invocation (g_ovf_n starts 0
    // from static init, so every call sees a clean counter; also aligns the
    // ncu -s 5 skip onto the gather kernel).
    ss_gather_kernel<<<SS_B * 16 * 16, 256, SMEM_BYTES>>>(img, flow, out);
    ss_ovf_kernel<<<512, 256>>>(img, out);
    ss_reset_kernel<<<1, 1>>>();
}